// round 16
// baseline (speedup 1.0000x reference)
#include <cuda_runtime.h>
#include <math.h>

// ---------------- problem constants ----------------
#define TSTEPS 1000
#define NIN    4096
#define RN     4000
#define OUTW   (2*RN)
#define ALPHA  0.5f

// ---------------- dual-chain pipeline config ----------------
#define NBLK   125             // 125 tiles x 32 columns = 4000
#define NTHR   1024
#define LAG    256             // chain2 trails chain1
#define TTOT   (TSTEPS + LAG)  // 1256 ticks

#define NNZ_CAP 1800000

// ---------------- device scratch ----------------
__device__ float          d_vals1[NNZ_CAP];
__device__ unsigned short d_rows1[NNZ_CAP];
__device__ float          d_vals2[NNZ_CAP];
__device__ unsigned short d_rows2[NNZ_CAP];
__device__ int            d_colptr1[RN+1];
__device__ int            d_colptr2[RN+1];
__device__ int            d_cntW1[8*RN];
__device__ int            d_cntW2[8*RN];
__device__ float          d_U1[TSTEPS*RN];    // x @ Win1  (prior launch -> RO)
__device__ float          d_U2[TSTEPS*RN];    // V1 @ Win2 (block-local produce/consume)
__device__ float          d_v1[2][RN];        // hot ping-pong states
__device__ float          d_v2[2][RN];
__device__ unsigned       g_ctr;              // tick barrier counter

// ---------------- packed f32x2 helpers -----------------
__device__ __forceinline__ unsigned long long dupf2(float v) {
    unsigned long long r;
    asm("mov.b64 %0, {%1, %2};" : "=l"(r) : "f"(v), "f"(v));
    return r;
}
__device__ __forceinline__ void fmaf2(unsigned long long &d,
                                      unsigned long long a,
                                      unsigned long long b) {
    asm("fma.rn.f32x2 %0, %1, %2, %0;" : "+l"(d) : "l"(a), "l"(b));
}
__device__ __forceinline__ float2 unpk(unsigned long long v) {
    float2 r;
    asm("mov.b64 {%0, %1}, %2;" : "=f"(r.x), "=f"(r.y) : "l"(v));
    return r;
}

// ---------------- scoped sync primitives ----------------
__device__ __forceinline__ void redAddRel(unsigned* p) {
    asm volatile("red.release.gpu.global.add.u32 [%0], 1;"
                 :: "l"(p) : "memory");
}
__device__ __forceinline__ unsigned ldAcq(const unsigned* p) {
    unsigned v;
    asm volatile("ld.acquire.gpu.global.u32 %0, [%1];"
                 : "=r"(v) : "l"(p) : "memory");
    return v;
}

// ---------------- count kernel (also resets barrier counter) ----------------
__global__ void countKernel(const float* __restrict__ W1,
                            const float* __restrict__ W2) {
    int b = blockIdx.x;
    if (b == 0 && threadIdx.x == 0) g_ctr = 0u;
    const float* W; int* cntW; int j0;
    if (b < 125) { W = W1; cntW = d_cntW1; j0 = b * 32; }
    else         { W = W2; cntW = d_cntW2; j0 = (b - 125) * 32; }
    int w = threadIdx.x >> 5, lane = threadIdx.x & 31;
    int j = j0 + lane;
    int c = 0;
    int i0 = w * 500, i1 = i0 + 500;
    for (int i = i0; i < i1; i++) c += (W[(size_t)i * RN + j] != 0.f);
    cntW[w * RN + j] = c;
}

// ---------------- exclusive scan ----------------
__global__ void scanKernel() {
    __shared__ int sA[4096], sB[4096];
    const int* cntW = (blockIdx.x == 0) ? d_cntW1 : d_cntW2;
    int* colptr     = (blockIdx.x == 0) ? d_colptr1 : d_colptr2;
    int tid = threadIdx.x;
    for (int i = tid; i < 4096; i += blockDim.x) {
        int tot = 0;
        if (i < RN)
            for (int w = 0; w < 8; w++) tot += cntW[w * RN + i];
        sA[i] = tot;
    }
    __syncthreads();
    int* src = sA; int* dst = sB;
    for (int off = 1; off < 4096; off <<= 1) {
        for (int i = tid; i < 4096; i += blockDim.x)
            dst[i] = src[i] + (i >= off ? src[i - off] : 0);
        __syncthreads();
        int* t = src; src = dst; dst = t;
    }
    for (int i = tid; i < RN; i += blockDim.x) colptr[i + 1] = src[i];
    if (tid == 0) colptr[0] = 0;
}

// ---------------- GEMM1 tile body: d_U1[128x128 tile] = x @ Win1 ------------
__device__ void gemm1_tile(const float* __restrict__ A,
                           const float* __restrict__ B,
                           int row0, int col0) {
    const int M = TSTEPS, N = RN, K = NIN, lda = NIN, ldb = RN, ldc = RN;
    float* __restrict__ C = d_U1;
    __shared__ float As[8][128];
    __shared__ float Bs[8][128];
    int tid = threadIdx.x;
    int tx = tid % 16, ty = tid / 16;

    unsigned long long acc2[4][8];
#pragma unroll
    for (int p = 0; p < 4; p++)
#pragma unroll
        for (int j = 0; j < 8; j++) acc2[p][j] = 0ull;

    const int aRow = tid >> 1;
    const int aCol = (tid & 1) * 4;
    const int bRow = tid >> 5;
    const int bCol = (tid & 31) * 4;

    float4 a4 = make_float4(0.f, 0.f, 0.f, 0.f);
    if (row0 + aRow < M)
        a4 = *(const float4*)(A + (size_t)(row0 + aRow) * lda + aCol);
    float4 b4 = make_float4(0.f, 0.f, 0.f, 0.f);
    if (col0 + bCol < N)
        b4 = *(const float4*)(B + (size_t)bRow * ldb + col0 + bCol);

    for (int k0 = 0; k0 < K; k0 += 8) {
        As[aCol + 0][aRow] = a4.x; As[aCol + 1][aRow] = a4.y;
        As[aCol + 2][aRow] = a4.z; As[aCol + 3][aRow] = a4.w;
        *(float4*)(&Bs[bRow][bCol]) = b4;
        __syncthreads();

        if (k0 + 8 < K) {
            if (row0 + aRow < M)
                a4 = *(const float4*)(A + (size_t)(row0 + aRow) * lda + k0 + 8 + aCol);
            if (col0 + bCol < N)
                b4 = *(const float4*)(B + (size_t)(k0 + 8 + bRow) * ldb + col0 + bCol);
        }

#pragma unroll
        for (int kk = 0; kk < 8; kk++) {
            float4 a0 = *(const float4*)(&As[kk][ty * 4]);
            float4 a1 = *(const float4*)(&As[kk][64 + ty * 4]);
            float4 bb0 = *(const float4*)(&Bs[kk][tx * 4]);
            float4 bb1 = *(const float4*)(&Bs[kk][64 + tx * 4]);
            unsigned long long ap[4];
            ap[0] = reinterpret_cast<const ulonglong2*>(&a0)->x;
            ap[1] = reinterpret_cast<const ulonglong2*>(&a0)->y;
            ap[2] = reinterpret_cast<const ulonglong2*>(&a1)->x;
            ap[3] = reinterpret_cast<const ulonglong2*>(&a1)->y;
            unsigned long long bd[8];
            bd[0] = dupf2(bb0.x); bd[1] = dupf2(bb0.y);
            bd[2] = dupf2(bb0.z); bd[3] = dupf2(bb0.w);
            bd[4] = dupf2(bb1.x); bd[5] = dupf2(bb1.y);
            bd[6] = dupf2(bb1.z); bd[7] = dupf2(bb1.w);
#pragma unroll
            for (int p = 0; p < 4; p++)
#pragma unroll
                for (int j = 0; j < 8; j++)
                    fmaf2(acc2[p][j], ap[p], bd[j]);
        }
        __syncthreads();
    }

#pragma unroll
    for (int p = 0; p < 4; p++) {
        float2 u[8];
#pragma unroll
        for (int j = 0; j < 8; j++) u[j] = unpk(acc2[p][j]);
#pragma unroll
        for (int h = 0; h < 2; h++) {
            int i = 2 * p + h;
            int r = row0 + ((i < 4) ? (ty * 4 + i) : (64 + ty * 4 + i - 4));
            if (r >= M) continue;
            float4 v0 = make_float4(h ? u[0].y : u[0].x, h ? u[1].y : u[1].x,
                                    h ? u[2].y : u[2].x, h ? u[3].y : u[3].x);
            float4 v1 = make_float4(h ? u[4].y : u[4].x, h ? u[5].y : u[5].x,
                                    h ? u[6].y : u[6].x, h ? u[7].y : u[7].x);
            int c0 = col0 + tx * 4;
            int c1 = col0 + 64 + tx * 4;
            if (c0 < N) *(float4*)(C + (size_t)r * ldc + c0) = v0;
            if (c1 < N) *(float4*)(C + (size_t)r * ldc + c1) = v1;
        }
    }
}

// ---------------- fused kernel: fill roles + GEMM1 roles --------------------
__global__ __launch_bounds__(256, 2) void fillGemm1Kernel(
        const float* __restrict__ W1, const float* __restrict__ W2,
        const float* __restrict__ x,  const float* __restrict__ Win1) {
    int b = blockIdx.x;
    if (b < 250) {
        const float* W; const int* cntW; const int* colptr;
        float* vals; unsigned short* rows; int j0;
        if (b < 125) { W = W1; cntW = d_cntW1; colptr = d_colptr1;
                       vals = d_vals1; rows = d_rows1; j0 = b * 32; }
        else         { W = W2; cntW = d_cntW2; colptr = d_colptr2;
                       vals = d_vals2; rows = d_rows2; j0 = (b - 125) * 32; }
        int w = threadIdx.x >> 5, lane = threadIdx.x & 31;
        int j = j0 + lane;
        int p = colptr[j];
        for (int w2 = 0; w2 < 8; w2++)
            if (w2 < w) p += cntW[w2 * RN + j];
        int i0 = w * 500, i1 = i0 + 500;
        for (int i = i0; i < i1; i++) {
            float v = W[(size_t)i * RN + j];
            if (v != 0.f) { vals[p] = v; rows[p] = (unsigned short)i; p++; }
        }
    } else {
        int p = b - 250;                   // 0..255
        gemm1_tile(x, Win1, (p >> 5) * 128, (p & 31) * 128);
    }
}

// ---------------- fused dual-chain + in-loop GEMM2 kernel -------------------
// Block b owns columns [b*32, b*32+32) of BOTH reservoirs AND of U2.
// Tick k: chain1 step t1=k; chain2 step t2=k-LAG; plus one GEMM2 k-slice:
//   U2 rowblock R (rows 128R..128R+127) accumulates 32 k-indices per tick
//   over ticks [128R+128, 128R+252]; write to d_U2 at phase end (ph==124).
//   Chain2 reads U2 row t2 at tick t2+LAG >= write tick + 4 (same block!).
// One grid barrier per tick (RED + counter poll, R10-proven).
__global__ __launch_bounds__(NTHR, 1) void dualKernel(
        const float* __restrict__ Win2, float* __restrict__ out) {
    __shared__ float vs1[RN];
    __shared__ float vs2[RN];
    __shared__ float asl[128 * 32];      // V1 slice, XOR-swizzled rows
    __shared__ int s_c1[33];
    __shared__ int s_c2[33];

    const int tid  = threadIdx.x;
    const int lane = tid & 31;
    const int wrp  = tid >> 5;           // 0..31 -> one column (both chains)
    const int j0   = blockIdx.x * 32;
    const int jcol = j0 + wrp;

    // GEMM mapping: thread -> (row, col-quad) of the 128x32 U2 tile
    const int grow = tid >> 3;           // 0..127
    const int gq   = tid & 7;            // 0..7 (4 cols each)
    const int gsw  = (grow & 3) << 3;    // bank swizzle
    unsigned long long acc01 = 0ull, acc23 = 0ull;

    if (tid < 33)      s_c1[tid]      = __ldg(&d_colptr1[j0 + tid]);
    else if (tid < 66) s_c2[tid - 33] = __ldg(&d_colptr2[j0 + tid - 33]);

    for (int k = 0; k < TTOT; k++) {
        const int t1 = k;
        const int t2 = k - LAG;

        // GEMM phase bookkeeping
        int R = -1, ph = 0, k0 = 0;
        if (k >= 128) {
            int kk = k - 128;
            int r_ = kk >> 7;
            ph = kk & 127;
            if (ph < 125 && r_ < 8) { R = r_; k0 = ph << 5; }
        }

        // prefetch U terms (off the staging critical path)
        float u1 = 0.f, u2v = 0.f;
        if (lane == 0) {
            if (t1 < TSTEPS) u1 = __ldg(&d_U1[(size_t)t1 * RN + jcol]);
            if (t2 >= 0)     u2v = d_U2[(size_t)t2 * RN + jcol]; // own block wrote it
        }

        // stage previous states (L1 bypass: written by other SMs)
        if (t1 >= 1 && t1 < TSTEPS && tid < RN / 4) {
            const float4* vp = reinterpret_cast<const float4*>(d_v1[(t1 - 1) & 1]);
            reinterpret_cast<float4*>(vs1)[tid] = __ldcg(vp + tid);
        }
        if (t2 >= 1 && t2 < TSTEPS && tid < RN / 4) {
            const float4* vp = reinterpret_cast<const float4*>(d_v2[(t2 - 1) & 1]);
            reinterpret_cast<float4*>(vs2)[tid] = __ldcg(vp + tid);
        }
        // stage A-slice: V1[128R+row][k0..k0+31] from out (cross-block, HB via barrier)
        if (R >= 0) {
            int vrow = (R << 7) + grow;
            float4 a4 = make_float4(0.f, 0.f, 0.f, 0.f);
            if (vrow < TSTEPS)
                a4 = __ldcg(reinterpret_cast<const float4*>(
                         out + (size_t)vrow * OUTW + k0 + gq * 4));
            int cb = (gq * 4) ^ gsw;     // swizzle preserves 4-groups
            *reinterpret_cast<float4*>(&asl[grow * 32 + cb]) = a4;
        }
        __syncthreads();

        float vn2 = 0.f;
        // ---- chain1: warp w -> column j0+w ----
        if (t1 < TSTEPS) {
            float acc = 0.f;
            if (t1 > 0) {
                const int ps = s_c1[wrp], pe = s_c1[wrp + 1];
#pragma unroll 4
                for (int p = ps + lane; p < pe; p += 32)
                    acc += __ldg(&d_vals1[p]) * vs1[__ldg(&d_rows1[p])];
#pragma unroll
                for (int off = 16; off > 0; off >>= 1)
                    acc += __shfl_down_sync(0xffffffffu, acc, off);
            }
            if (lane == 0) {
                float vn1 = (t1 > 0)
                          ? (1.f - ALPHA) * vs1[jcol] + ALPHA * tanhf(acc + u1)
                          : ALPHA * tanhf(u1);
                d_v1[t1 & 1][jcol] = vn1;
                out[(size_t)t1 * OUTW + jcol] = vn1;   // PRE-barrier: A-slice HB
            }
        }
        // ---- chain2: warp w -> column j0+w ----
        if (t2 >= 0) {
            float acc = 0.f;
            if (t2 > 0) {
                const int ps = s_c2[wrp], pe = s_c2[wrp + 1];
#pragma unroll 4
                for (int p = ps + lane; p < pe; p += 32)
                    acc += __ldg(&d_vals2[p]) * vs2[__ldg(&d_rows2[p])];
#pragma unroll
                for (int off = 16; off > 0; off >>= 1)
                    acc += __shfl_down_sync(0xffffffffu, acc, off);
            }
            if (lane == 0) {
                vn2 = (t2 > 0)
                    ? (1.f - ALPHA) * vs2[jcol] + ALPHA * tanhf(acc + u2v)
                    : ALPHA * tanhf(u2v);
                d_v2[t2 & 1][jcol] = vn2;
            }
        }
        // ---- GEMM2 slice: acc += V1[128R+row][k0..k0+32) * Win2[k0..][cols] --
        if (R >= 0) {
            const float* wrow = Win2 + (size_t)k0 * RN + j0 + gq * 4;
            const float* ap = asl + grow * 32;
#pragma unroll 8
            for (int kk = 0; kk < 32; kk++) {
                float a = ap[kk ^ gsw];
                float4 w4 = __ldg(reinterpret_cast<const float4*>(
                                wrow + (size_t)kk * RN));
                unsigned long long ad = dupf2(a);
                fmaf2(acc01, ad, reinterpret_cast<const ulonglong2*>(&w4)->x);
                fmaf2(acc23, ad, reinterpret_cast<const ulonglong2*>(&w4)->y);
            }
            if (ph == 124) {              // phase end: commit U2 rowblock
                int vrow = (R << 7) + grow;
                if (vrow < TSTEPS) {
                    float2 lo = unpk(acc01), hi = unpk(acc23);
                    *reinterpret_cast<float4*>(
                        d_U2 + (size_t)vrow * RN + j0 + gq * 4)
                        = make_float4(lo.x, lo.y, hi.x, hi.y);
                }
                acc01 = 0ull; acc23 = 0ull;
            }
        }

        // ---- tick barrier ----
        if (k < TTOT - 1) {
            __syncthreads();
            if (tid == 0) {
                redAddRel(&g_ctr);
                unsigned target = (unsigned)(k + 1) * (unsigned)NBLK;
                while (ldAcq(&g_ctr) < target) { }
            }
            __syncthreads();
        }

        // archive chain2 output AFTER barrier (never re-read in this kernel)
        if (t2 >= 0 && lane == 0)
            out[(size_t)t2 * OUTW + RN + jcol] = vn2;
    }
}

// ---------------- launch ----------------
extern "C" void kernel_launch(void* const* d_in, const int* in_sizes, int n_in,
                              void* d_out, int out_size) {
    const float* x    = (const float*)d_in[0];
    const float* Win1 = (const float*)d_in[1];
    const float* W1   = (const float*)d_in[2];
    const float* Win2 = (const float*)d_in[3];
    const float* W2   = (const float*)d_in[4];
    float* out = (float*)d_out;
    (void)in_sizes; (void)n_in; (void)out_size;

    countKernel<<<250, 256>>>(W1, W2);               // + barrier-counter reset
    scanKernel<<<2, 1024>>>();
    fillGemm1Kernel<<<506, 256>>>(W1, W2, x, Win1);  // fill || GEMM1

    // fused dual-chain + in-loop GEMM2: everything else in one kernel
    dualKernel<<<NBLK, NTHR>>>(Win2, out);
}

// round 17
// speedup vs baseline: 1.2378x; 1.2378x over previous
#include <cuda_runtime.h>
#include <math.h>

// ---------------- problem constants ----------------
#define TSTEPS 1000
#define NIN    4096
#define RN     4000
#define OUTW   (2*RN)
#define ALPHA  0.5f

// ---------------- persistent loop config (R10/R15-proven) ----------------
#define NBLK   125             // 125 tiles x 32 columns = 4000
#define NTHR   1024

#define NNZ_CAP 1800000

// ---------------- device scratch ----------------
__device__ float          d_vals1[NNZ_CAP];
__device__ unsigned short d_rows1[NNZ_CAP];
__device__ float          d_vals2[NNZ_CAP];
__device__ unsigned short d_rows2[NNZ_CAP];
__device__ int            d_colptr1[RN+1];
__device__ int            d_colptr2[RN+1];
__device__ int            d_cntW1[8*RN];
__device__ int            d_cntW2[8*RN];
__device__ float          d_U1[TSTEPS*RN];    // x @ Win1   (16 MB)
__device__ float          d_U2[TSTEPS*RN];    // V1 @ Win2  (16 MB)
__device__ float          d_v[2][RN];         // hot ping-pong state
__device__ unsigned       g_ctr1;             // monotonic barrier counters
__device__ unsigned       g_ctr2;

// ---------------- packed f32x2 helpers (sm_103a FFMA2 pipe) -----------------
__device__ __forceinline__ unsigned long long dupf2(float v) {
    unsigned long long r;
    asm("mov.b64 %0, {%1, %2};" : "=l"(r) : "f"(v), "f"(v));
    return r;
}
__device__ __forceinline__ void fmaf2(unsigned long long &d,
                                      unsigned long long a,
                                      unsigned long long b) {
    asm("fma.rn.f32x2 %0, %1, %2, %0;" : "+l"(d) : "l"(a), "l"(b));
}
__device__ __forceinline__ float2 unpk(unsigned long long v) {
    float2 r;
    asm("mov.b64 {%0, %1}, %2;" : "=f"(r.x), "=f"(r.y) : "l"(v));
    return r;
}

// ---------------- scoped sync primitives ----------------
__device__ __forceinline__ void redAddRel(unsigned* p) {
    asm volatile("red.release.gpu.global.add.u32 [%0], 1;"
                 :: "l"(p) : "memory");
}
__device__ __forceinline__ unsigned ldAcq(const unsigned* p) {
    unsigned v;
    asm volatile("ld.acquire.gpu.global.u32 %0, [%1];"
                 : "=r"(v) : "l"(p) : "memory");
    return v;
}
__device__ __forceinline__ unsigned ldRlx(const unsigned* p) {
    unsigned v;
    asm volatile("ld.relaxed.gpu.global.u32 %0, [%1];"
                 : "=r"(v) : "l"(p) : "memory");
    return v;
}

// ---------------- count kernel (also resets barrier counters) ---------------
__global__ void countKernel(const float* __restrict__ W1,
                            const float* __restrict__ W2) {
    int b = blockIdx.x;
    if (b == 0 && threadIdx.x == 0) { g_ctr1 = 0u; g_ctr2 = 0u; }
    const float* W; int* cntW; int j0;
    if (b < 125) { W = W1; cntW = d_cntW1; j0 = b * 32; }
    else         { W = W2; cntW = d_cntW2; j0 = (b - 125) * 32; }
    int w = threadIdx.x >> 5, lane = threadIdx.x & 31;
    int j = j0 + lane;
    int c = 0;
    int i0 = w * 500, i1 = i0 + 500;
    for (int i = i0; i < i1; i++) c += (W[(size_t)i * RN + j] != 0.f);
    cntW[w * RN + j] = c;
}

// ---------------- exclusive scan ----------------
__global__ void scanKernel() {
    __shared__ int sA[4096], sB[4096];
    const int* cntW = (blockIdx.x == 0) ? d_cntW1 : d_cntW2;
    int* colptr     = (blockIdx.x == 0) ? d_colptr1 : d_colptr2;
    int tid = threadIdx.x;
    for (int i = tid; i < 4096; i += blockDim.x) {
        int tot = 0;
        if (i < RN)
            for (int w = 0; w < 8; w++) tot += cntW[w * RN + i];
        sA[i] = tot;
    }
    __syncthreads();
    int* src = sA; int* dst = sB;
    for (int off = 1; off < 4096; off <<= 1) {
        for (int i = tid; i < 4096; i += blockDim.x)
            dst[i] = src[i] + (i >= off ? src[i - off] : 0);
        __syncthreads();
        int* t = src; src = dst; dst = t;
    }
    for (int i = tid; i < RN; i += blockDim.x) colptr[i + 1] = src[i];
    if (tid == 0) colptr[0] = 0;
}

// ---------------- GEMM1 tile body: d_U1[128x128 tile] = x @ Win1 ------------
__device__ void gemm1_tile(const float* __restrict__ A,
                           const float* __restrict__ B,
                           int row0, int col0) {
    const int M = TSTEPS, N = RN, K = NIN, lda = NIN, ldb = RN, ldc = RN;
    float* __restrict__ C = d_U1;
    __shared__ float As[8][128];
    __shared__ float Bs[8][128];
    int tid = threadIdx.x;
    int tx = tid % 16, ty = tid / 16;

    unsigned long long acc2[4][8];
#pragma unroll
    for (int p = 0; p < 4; p++)
#pragma unroll
        for (int j = 0; j < 8; j++) acc2[p][j] = 0ull;

    const int aRow = tid >> 1;
    const int aCol = (tid & 1) * 4;
    const int bRow = tid >> 5;
    const int bCol = (tid & 31) * 4;

    float4 a4 = make_float4(0.f, 0.f, 0.f, 0.f);
    if (row0 + aRow < M)
        a4 = *(const float4*)(A + (size_t)(row0 + aRow) * lda + aCol);
    float4 b4 = make_float4(0.f, 0.f, 0.f, 0.f);
    if (col0 + bCol < N)
        b4 = *(const float4*)(B + (size_t)bRow * ldb + col0 + bCol);

    for (int k0 = 0; k0 < K; k0 += 8) {
        As[aCol + 0][aRow] = a4.x; As[aCol + 1][aRow] = a4.y;
        As[aCol + 2][aRow] = a4.z; As[aCol + 3][aRow] = a4.w;
        *(float4*)(&Bs[bRow][bCol]) = b4;
        __syncthreads();

        if (k0 + 8 < K) {
            if (row0 + aRow < M)
                a4 = *(const float4*)(A + (size_t)(row0 + aRow) * lda + k0 + 8 + aCol);
            if (col0 + bCol < N)
                b4 = *(const float4*)(B + (size_t)(k0 + 8 + bRow) * ldb + col0 + bCol);
        }

#pragma unroll
        for (int kk = 0; kk < 8; kk++) {
            float4 a0 = *(const float4*)(&As[kk][ty * 4]);
            float4 a1 = *(const float4*)(&As[kk][64 + ty * 4]);
            float4 bb0 = *(const float4*)(&Bs[kk][tx * 4]);
            float4 bb1 = *(const float4*)(&Bs[kk][64 + tx * 4]);
            unsigned long long ap[4];
            ap[0] = reinterpret_cast<const ulonglong2*>(&a0)->x;
            ap[1] = reinterpret_cast<const ulonglong2*>(&a0)->y;
            ap[2] = reinterpret_cast<const ulonglong2*>(&a1)->x;
            ap[3] = reinterpret_cast<const ulonglong2*>(&a1)->y;
            unsigned long long bd[8];
            bd[0] = dupf2(bb0.x); bd[1] = dupf2(bb0.y);
            bd[2] = dupf2(bb0.z); bd[3] = dupf2(bb0.w);
            bd[4] = dupf2(bb1.x); bd[5] = dupf2(bb1.y);
            bd[6] = dupf2(bb1.z); bd[7] = dupf2(bb1.w);
#pragma unroll
            for (int p = 0; p < 4; p++)
#pragma unroll
                for (int j = 0; j < 8; j++)
                    fmaf2(acc2[p][j], ap[p], bd[j]);
        }
        __syncthreads();
    }

#pragma unroll
    for (int p = 0; p < 4; p++) {
        float2 u[8];
#pragma unroll
        for (int j = 0; j < 8; j++) u[j] = unpk(acc2[p][j]);
#pragma unroll
        for (int h = 0; h < 2; h++) {
            int i = 2 * p + h;
            int r = row0 + ((i < 4) ? (ty * 4 + i) : (64 + ty * 4 + i - 4));
            if (r >= M) continue;
            float4 v0 = make_float4(h ? u[0].y : u[0].x, h ? u[1].y : u[1].x,
                                    h ? u[2].y : u[2].x, h ? u[3].y : u[3].x);
            float4 v1 = make_float4(h ? u[4].y : u[4].x, h ? u[5].y : u[5].x,
                                    h ? u[6].y : u[6].x, h ? u[7].y : u[7].x);
            int c0 = col0 + tx * 4;
            int c1 = col0 + 64 + tx * 4;
            if (c0 < N) *(float4*)(C + (size_t)r * ldc + c0) = v0;
            if (c1 < N) *(float4*)(C + (size_t)r * ldc + c1) = v1;
        }
    }
}

// ---------------- fused kernel: fill roles + GEMM1 roles --------------------
__global__ __launch_bounds__(256, 2) void fillGemm1Kernel(
        const float* __restrict__ W1, const float* __restrict__ W2,
        const float* __restrict__ x,  const float* __restrict__ Win1) {
    int b = blockIdx.x;
    if (b < 250) {
        const float* W; const int* cntW; const int* colptr;
        float* vals; unsigned short* rows; int j0;
        if (b < 125) { W = W1; cntW = d_cntW1; colptr = d_colptr1;
                       vals = d_vals1; rows = d_rows1; j0 = b * 32; }
        else         { W = W2; cntW = d_cntW2; colptr = d_colptr2;
                       vals = d_vals2; rows = d_rows2; j0 = (b - 125) * 32; }
        int w = threadIdx.x >> 5, lane = threadIdx.x & 31;
        int j = j0 + lane;
        int p = colptr[j];
        for (int w2 = 0; w2 < 8; w2++)
            if (w2 < w) p += cntW[w2 * RN + j];
        int i0 = w * 500, i1 = i0 + 500;
        for (int i = i0; i < i1; i++) {
            float v = W[(size_t)i * RN + j];
            if (v != 0.f) { vals[p] = v; rows[p] = (unsigned short)i; p++; }
        }
    } else {
        int p = b - 250;                   // 0..255
        gemm1_tile(x, Win1, (p >> 5) * 128, (p & 31) * 128);
    }
}

// ---------------- SGEMM2 (separate launch): d_U2 = V1 @ Win2 ----------------
__global__ __launch_bounds__(256, 2) void sgemm2K(const float* __restrict__ A,
                                                  const float* __restrict__ B,
                                                  int M, int N, int K,
                                                  int lda, int ldb, int ldc) {
    float* __restrict__ C = d_U2;
    __shared__ float As[8][128];
    __shared__ float Bs[8][128];
    int tid = threadIdx.x;
    int tx = tid % 16, ty = tid / 16;
    int row0 = blockIdx.y * 128, col0 = blockIdx.x * 128;

    unsigned long long acc2[4][8];
#pragma unroll
    for (int p = 0; p < 4; p++)
#pragma unroll
        for (int j = 0; j < 8; j++) acc2[p][j] = 0ull;

    const int aRow = tid >> 1;
    const int aCol = (tid & 1) * 4;
    const int bRow = tid >> 5;
    const int bCol = (tid & 31) * 4;

    float4 a4 = make_float4(0.f, 0.f, 0.f, 0.f);
    if (row0 + aRow < M)
        a4 = *(const float4*)(A + (size_t)(row0 + aRow) * lda + aCol);
    float4 b4 = make_float4(0.f, 0.f, 0.f, 0.f);
    if (col0 + bCol < N)
        b4 = *(const float4*)(B + (size_t)bRow * ldb + col0 + bCol);

    for (int k0 = 0; k0 < K; k0 += 8) {
        As[aCol + 0][aRow] = a4.x; As[aCol + 1][aRow] = a4.y;
        As[aCol + 2][aRow] = a4.z; As[aCol + 3][aRow] = a4.w;
        *(float4*)(&Bs[bRow][bCol]) = b4;
        __syncthreads();

        if (k0 + 8 < K) {
            if (row0 + aRow < M)
                a4 = *(const float4*)(A + (size_t)(row0 + aRow) * lda + k0 + 8 + aCol);
            if (col0 + bCol < N)
                b4 = *(const float4*)(B + (size_t)(k0 + 8 + bRow) * ldb + col0 + bCol);
        }

#pragma unroll
        for (int kk = 0; kk < 8; kk++) {
            float4 a0 = *(const float4*)(&As[kk][ty * 4]);
            float4 a1 = *(const float4*)(&As[kk][64 + ty * 4]);
            float4 bb0 = *(const float4*)(&Bs[kk][tx * 4]);
            float4 bb1 = *(const float4*)(&Bs[kk][64 + tx * 4]);
            unsigned long long ap[4];
            ap[0] = reinterpret_cast<const ulonglong2*>(&a0)->x;
            ap[1] = reinterpret_cast<const ulonglong2*>(&a0)->y;
            ap[2] = reinterpret_cast<const ulonglong2*>(&a1)->x;
            ap[3] = reinterpret_cast<const ulonglong2*>(&a1)->y;
            unsigned long long bd[8];
            bd[0] = dupf2(bb0.x); bd[1] = dupf2(bb0.y);
            bd[2] = dupf2(bb0.z); bd[3] = dupf2(bb0.w);
            bd[4] = dupf2(bb1.x); bd[5] = dupf2(bb1.y);
            bd[6] = dupf2(bb1.z); bd[7] = dupf2(bb1.w);
#pragma unroll
            for (int p = 0; p < 4; p++)
#pragma unroll
                for (int j = 0; j < 8; j++)
                    fmaf2(acc2[p][j], ap[p], bd[j]);
        }
        __syncthreads();
    }

#pragma unroll
    for (int p = 0; p < 4; p++) {
        float2 u[8];
#pragma unroll
        for (int j = 0; j < 8; j++) u[j] = unpk(acc2[p][j]);
#pragma unroll
        for (int h = 0; h < 2; h++) {
            int i = 2 * p + h;
            int r = row0 + ((i < 4) ? (ty * 4 + i) : (64 + ty * 4 + i - 4));
            if (r >= M) continue;
            float4 v0 = make_float4(h ? u[0].y : u[0].x, h ? u[1].y : u[1].x,
                                    h ? u[2].y : u[2].x, h ? u[3].y : u[3].x);
            float4 v1 = make_float4(h ? u[4].y : u[4].x, h ? u[5].y : u[5].x,
                                    h ? u[6].y : u[6].x, h ? u[7].y : u[7].x);
            int c0 = col0 + tx * 4;
            int c1 = col0 + 64 + tx * 4;
            if (c0 < N) *(float4*)(C + (size_t)r * ldc + c0) = v0;
            if (c1 < N) *(float4*)(C + (size_t)r * ldc + c1) = v1;
        }
    }
}

// ---------------- grid barrier: RED arrival + RELAXED poll + acquire --------
// Poll with ld.relaxed (no per-poll ordering cost); once the counter reaches
// target, a single ld.acquire establishes synchronizes-with against every
// releasing red.release (counter is monotonic, so the acquire re-read is
// guaranteed >= target).
__device__ __forceinline__ void gsyncC(unsigned target, unsigned* ctr) {
    __syncthreads();
    if (threadIdx.x == 0) {
        redAddRel(ctr);                       // fire-and-forget arrival
        while (ldRlx(ctr) < target) { }       // cheap relaxed spin
        (void)ldAcq(ctr);                     // one acquire: HB established
    }
    __syncthreads();
}

// ---------------- sparse-only recurrence (R15-proven + U prefetch) ----------
// Block b owns columns [b*32, b*32+32). CSC slice is L1-resident after step 1.
// v(t) = 0.5*v(t-1) + 0.5*tanh( v(t-1)@W + U[t] ),  v(-1)=0
// U[t+1] is prefetched BEFORE the barrier of step t (U is kernel-lifetime RO),
// hiding its L2 latency under the barrier wait. Archive stores stay after
// arrival (read only by later launches).
__device__ __forceinline__ void esn_chain(const int* __restrict__ colptr,
                                          const float* __restrict__ gvals,
                                          const unsigned short* __restrict__ grows,
                                          const float* __restrict__ U,
                                          float* __restrict__ out, int ofs,
                                          unsigned* ctr) {
    __shared__ float vs[RN];
    __shared__ int s_cst[33];

    const int tid  = threadIdx.x;
    const int lane = tid & 31;
    const int wrp  = tid >> 5;          // 0..31 -> one column each
    const int j0   = blockIdx.x * 32;
    const int jcol = j0 + wrp;

    if (tid < 33) s_cst[tid] = __ldg(&colptr[j0 + tid]);

    // t = 0 : v(0) = 0.5*tanh(U[0]); prefetch U[1] before the barrier
    float vn_keep = 0.f, uval = 0.f;
    if (lane == 0) {
        vn_keep = ALPHA * tanhf(__ldg(&U[jcol]));
        d_v[0][jcol] = vn_keep;
        uval = __ldg(&U[(size_t)1 * RN + jcol]);     // prefetch for t=1
    }
    gsyncC(1u * NBLK, ctr);             // also orders s_cst for the loop
    if (lane == 0) out[(size_t)0 * OUTW + ofs + jcol] = vn_keep;  // archive

    for (int t = 1; t < TSTEPS; t++) {
        const float* __restrict__ vsrc = d_v[(t - 1) & 1];
        float*       __restrict__ vdst = d_v[t & 1];

        // stage v(t-1) into smem (bypass L1: written by other SMs)
        const float4* vp = reinterpret_cast<const float4*>(vsrc);
        for (int i = tid; i < RN / 4; i += NTHR)
            reinterpret_cast<float4*>(vs)[i] = __ldcg(vp + i);
        __syncthreads();

        // warp w -> column j0+w; hot publish before barrier
        {
            const int ps = s_cst[wrp];
            const int pe = s_cst[wrp + 1];
            float acc = 0.f;
#pragma unroll 4
            for (int p = ps + lane; p < pe; p += 32)
                acc += __ldg(&gvals[p]) * vs[__ldg(&grows[p])];
#pragma unroll
            for (int off = 16; off > 0; off >>= 1)
                acc += __shfl_down_sync(0xffffffffu, acc, off);
            if (lane == 0) {
                float z = acc + uval;
                vn_keep = (1.f - ALPHA) * vs[jcol] + ALPHA * tanhf(z);
                vdst[jcol] = vn_keep;                      // hot publish
                // prefetch U for t+1: L2 latency hidden under barrier wait
                if (t + 1 < TSTEPS)
                    uval = __ldg(&U[(size_t)(t + 1) * RN + jcol]);
            }
        }

        if (t < TSTEPS - 1)
            gsyncC((unsigned)(t + 1) * NBLK, ctr);

        // archive AFTER arrival: off the release-ordering path
        if (lane == 0) out[(size_t)t * OUTW + ofs + jcol] = vn_keep;
    }
}

__global__ __launch_bounds__(NTHR, 1) void esn1Kernel(float* __restrict__ out) {
    esn_chain(d_colptr1, d_vals1, d_rows1, d_U1, out, 0, &g_ctr1);
}

__global__ __launch_bounds__(NTHR, 1) void esn2Kernel(float* __restrict__ out) {
    esn_chain(d_colptr2, d_vals2, d_rows2, d_U2, out, RN, &g_ctr2);
}

// ---------------- launch ----------------
extern "C" void kernel_launch(void* const* d_in, const int* in_sizes, int n_in,
                              void* d_out, int out_size) {
    const float* x    = (const float*)d_in[0];
    const float* Win1 = (const float*)d_in[1];
    const float* W1   = (const float*)d_in[2];
    const float* Win2 = (const float*)d_in[3];
    const float* W2   = (const float*)d_in[4];
    float* out = (float*)d_out;
    (void)in_sizes; (void)n_in; (void)out_size;

    countKernel<<<250, 256>>>(W1, W2);               // + barrier-counter reset
    scanKernel<<<2, 1024>>>();
    fillGemm1Kernel<<<506, 256>>>(W1, W2, x, Win1);  // fill || GEMM1

    // v1 chain -> out[:, 0:4000]
    esn1Kernel<<<NBLK, NTHR>>>(out);

    // U2 = V1[1000,4000] @ Win2[4000,4000]  (V1 rows in out, stride OUTW)
    dim3 gg((RN + 127) / 128, (TSTEPS + 127) / 128);
    sgemm2K<<<gg, 256>>>(out, Win2, TSTEPS, RN, RN, OUTW, RN, RN);

    // v2 chain -> out[:, 4000:8000]
    esn2Kernel<<<NBLK, NTHR>>>(out);
}